// round 16
// baseline (speedup 1.0000x reference)
#include <cuda_runtime.h>
#include <cuda_bf16.h>
#include <cfloat>
#include <math.h>

#define B_   16
#define NPER 2048
#define NTOT (B_*NPER)
#define KNN  20

typedef unsigned long long ull;

// ---------------- scratch (device globals; no runtime allocation) ----------
__device__ float4 g_x0[NTOT];
__device__ float  g_sn[NTOT];
__device__ int    g_idx[NTOT*KNN];
__device__ float  g_x1[NTOT*64];
__device__ float  g_x2[NTOT*64];
__device__ float  g_x3[NTOT*128];
__device__ float  g_u2[NTOT*64];
__device__ float  g_y2[NTOT*64];
__device__ float  g_u3[NTOT*128];
__device__ float  g_y3[NTOT*128];
__device__ float  g_out2[B_*1024];
__device__ float  g_h1[B_*512];
__device__ __align__(16) __nv_bfloat16 g_fhi[NTOT*256];
__device__ __align__(16) __nv_bfloat16 g_flo[NTOT*256];
__device__ __align__(16) __nv_bfloat16 g_whi[1024*256];
__device__ __align__(16) __nv_bfloat16 g_wlo[1024*256];

__device__ __forceinline__ void atomicMaxFloat(float* addr, float v){
    if (v >= 0.f) atomicMax((int*)addr, __float_as_int(v));
    else          atomicMin((unsigned int*)addr, (unsigned int)__float_as_int(v));
}
__device__ __forceinline__ unsigned packbf(__nv_bfloat16 a, __nv_bfloat16 b){
    __nv_bfloat162 t = __halves2bfloat162(a, b);
    return *reinterpret_cast<unsigned*>(&t);
}
__device__ __forceinline__ void split_bf(float x, __nv_bfloat16& h, __nv_bfloat16& l){
    h = __float2bfloat16(x);
    l = __float2bfloat16(x - __bfloat162float(h));
}
// order-preserving float<->uint encoding (total order, matches float <)
__device__ __forceinline__ unsigned encf(float f){
    unsigned b = __float_as_uint(f);
    return (b & 0x80000000u) ? ~b : (b | 0x80000000u);
}
__device__ __forceinline__ float decf(unsigned u){
    unsigned b = (u & 0x80000000u) ? (u & 0x7FFFFFFFu) : ~u;
    return __uint_as_float(b);
}
// mma.sync m16n8k16 bf16 (HMMA path, base sm_80+ feature)
__device__ __forceinline__ void mma_bf16(float* d, const unsigned* a, const unsigned* b){
    asm volatile("mma.sync.aligned.m16n8k16.row.col.f32.bf16.bf16.f32 "
        "{%0,%1,%2,%3}, {%4,%5,%6,%7}, {%8,%9}, {%0,%1,%2,%3};"
        : "+f"(d[0]), "+f"(d[1]), "+f"(d[2]), "+f"(d[3])
        : "r"(a[0]), "r"(a[1]), "r"(a[2]), "r"(a[3]), "r"(b[0]), "r"(b[1]));
}

// ---------------- prep: x0 + sn + out2 init (fused) -------------------------
__global__ __launch_bounds__(256) void prep_kernel(const float* __restrict__ pos,
                                                   const float* __restrict__ xf){
    int i = blockIdx.x*256 + threadIdx.x;
    float4 p = make_float4(pos[i*3+0], pos[i*3+1], pos[i*3+2], xf[i]);
    g_x0[i] = p;
    g_sn[i] = p.x*p.x + p.y*p.y + p.z*p.z + p.w*p.w;
    if (i < B_*1024) g_out2[i] = -FLT_MAX;
}

// ---------------- weight conversion: l1w -> bf16 hi/lo, [o][k] transposed ---
__global__ __launch_bounds__(256) void wconv_kernel(const float* __restrict__ l1w){
    int i = blockIdx.x*256 + threadIdx.x;    // 1024*256
    int o = i & 1023, k = i >> 10;
    float w = l1w[k*1024 + o];
    __nv_bfloat16 h, l; split_bf(w, h, l);
    g_whi[o*256 + k] = h;
    g_wlo[o*256 + k] = l;
}

// ---------------- kNN: warp per query, paired candidates + redux worst ------
__global__ __launch_bounds__(512) void knn_kernel()
{
    __shared__ float4 sp[NPER];
    __shared__ float  sn[NPER];
    const unsigned FULL = 0xFFFFFFFFu;
    int b    = blockIdx.x >> 7;
    int base = b * NPER;
    for (int j = threadIdx.x; j < NPER; j += 512){
        sp[j] = g_x0[base+j];
        sn[j] = g_sn[base+j];
    }
    __syncthreads();

    int lane = threadIdx.x & 31;
    int q    = (blockIdx.x & 127)*16 + (threadIdx.x >> 5);
    float4 p = sp[q];
    float  pn = sn[q];

    float bd = FLT_MAX;
    int   bi = 0;
    float worst = FLT_MAX;

    for (int s = 0; s < NPER; s += 64){
        int j0 = s + lane, j1 = s + 32 + lane;
        float4 c0 = sp[j0];
        float4 c1 = sp[j1];
        float d0 = pn + sn[j0] - 2.f*(p.x*c0.x + p.y*c0.y + p.z*c0.z + p.w*c0.w);
        float d1 = pn + sn[j1] - 2.f*(p.x*c1.x + p.y*c1.y + p.z*c1.z + p.w*c1.w);
        if (j0 == q) d0 = FLT_MAX;
        if (j1 == q) d1 = FLT_MAX;
        unsigned m = __ballot_sync(FULL, fminf(d0, d1) < worst);
        while (m){
            int src = __ffs(m) - 1; m &= m - 1;
            float e0 = __shfl_sync(FULL, d0, src);
            float e1 = __shfl_sync(FULL, d1, src);
            if (e0 < worst){
                unsigned wm = __ballot_sync(FULL, (lane < KNN) && (bd == worst));
                int slot = __ffs(wm) - 1;
                if (lane == slot){ bd = e0; bi = s + src; }
                worst = decf(__reduce_max_sync(FULL, (lane < KNN) ? encf(bd) : 0u));
            }
            if (e1 < worst){
                unsigned wm = __ballot_sync(FULL, (lane < KNN) && (bd == worst));
                int slot = __ffs(wm) - 1;
                if (lane == slot){ bd = e1; bi = s + 32 + src; }
                worst = decf(__reduce_max_sync(FULL, (lane < KNN) ? encf(bd) : 0u));
            }
        }
    }
    if (lane < KNN) g_idx[(base+q)*KNN + lane] = base + bi;
}

// ---------------- EdgeConv1 via HMMA (R15 proven) ---------------------------
__global__ __launch_bounds__(160) void conv1_kernel(
    const float* __restrict__ w1, const float* __restrict__ b1,
    const float* __restrict__ w2, const float* __restrict__ b2,
    const float* __restrict__ w3, const float* __restrict__ b3)
{
    const int S = 72;
    __shared__ __align__(16) __nv_bfloat16 sA[2*80*72];
    __shared__ __align__(16) __nv_bfloat16 sB[2*64*72];
    __shared__ float sW1b[4*64], sW1d[4*64], sb1v[64], sb2v[64], sb3v[64];
    __nv_bfloat16* sAhi = sA;
    __nv_bfloat16* sAlo = sA + 80*S;
    __nv_bfloat16* sBhi = sB;
    __nv_bfloat16* sBlo = sB + 64*S;
    float* sOut = (float*)sA;

    int tid = threadIdx.x, w = tid >> 5, l = tid & 31;

    for (int t = tid; t < 256; t += 160){
        int c = t >> 6, o = t & 63;
        float top = w1[c*64+o], bot = w1[(c+4)*64+o];
        sW1b[t] = bot; sW1d[t] = top - bot;
    }
    if (tid < 64){ sb1v[tid]=b1[tid]; sb2v[tid]=b2[tid]; sb3v[tid]=b3[tid]; }
    for (int t = tid; t < 4096; t += 160){
        int o = t & 63, k = t >> 6;
        __nv_bfloat16 h, lo2; split_bf(w2[k*64+o], h, lo2);
        sBhi[o*S+k] = h; sBlo[o*S+k] = lo2;
    }
    __syncthreads();

    {
        int row   = w*16 + (l>>1);
        int chalf = (l&1)*32;
        int node  = row / 20;
        int e     = row - node*20;
        int gi    = blockIdx.x*4 + node;
        int j     = g_idx[gi*KNN + e];
        float4 xi = g_x0[gi];
        float4 xj = g_x0[j];
        for (int c = chalf; c < chalf+32; c++){
            float v = sb1v[c]
                + xi.x*sW1d[c] + xi.y*sW1d[64+c] + xi.z*sW1d[128+c] + xi.w*sW1d[192+c]
                + xj.x*sW1b[c] + xj.y*sW1b[64+c] + xj.z*sW1b[128+c] + xj.w*sW1b[192+c];
            v = fmaxf(v, 0.f);
            __nv_bfloat16 h, lo2; split_bf(v, h, lo2);
            sAhi[row*S + c] = h;
            sAlo[row*S + c] = lo2;
        }
    }
    __syncthreads();

    float d[8][4];
    int r  = w*16 + (l>>2);
    int cb = (l&3)*2;

    for (int layer = 0; layer < 2; layer++){
        #pragma unroll
        for (int nt=0; nt<8; nt++)
            #pragma unroll
            for (int q=0;q<4;q++) d[nt][q] = 0.f;

        #pragma unroll
        for (int ks = 0; ks < 4; ks++){
            int kof = ks*16 + cb;
            unsigned ah[4], bh[8][2], bl2[8][2];
            ah[0] = *(const unsigned*)(sAhi + r*S     + kof);
            ah[1] = *(const unsigned*)(sAhi + (r+8)*S + kof);
            ah[2] = *(const unsigned*)(sAhi + r*S     + kof + 8);
            ah[3] = *(const unsigned*)(sAhi + (r+8)*S + kof + 8);
            #pragma unroll
            for (int nt=0; nt<8; nt++){
                int n = nt*8 + (l>>2);
                bh[nt][0]  = *(const unsigned*)(sBhi + n*S + kof);
                bh[nt][1]  = *(const unsigned*)(sBhi + n*S + kof + 8);
                bl2[nt][0] = *(const unsigned*)(sBlo + n*S + kof);
                bl2[nt][1] = *(const unsigned*)(sBlo + n*S + kof + 8);
            }
            #pragma unroll
            for (int nt=0; nt<8; nt++) mma_bf16(d[nt], ah, bh[nt]);
            #pragma unroll
            for (int nt=0; nt<8; nt++) mma_bf16(d[nt], ah, bl2[nt]);
            unsigned al[4];
            al[0] = *(const unsigned*)(sAlo + r*S     + kof);
            al[1] = *(const unsigned*)(sAlo + (r+8)*S + kof);
            al[2] = *(const unsigned*)(sAlo + r*S     + kof + 8);
            al[3] = *(const unsigned*)(sAlo + (r+8)*S + kof + 8);
            #pragma unroll
            for (int nt=0; nt<8; nt++) mma_bf16(d[nt], al, bh[nt]);
        }

        if (layer == 0){
            #pragma unroll
            for (int nt=0; nt<8; nt++){
                int c = nt*8 + cb;
                float v0 = fmaxf(d[nt][0] + sb2v[c],   0.f);
                float v1 = fmaxf(d[nt][1] + sb2v[c+1], 0.f);
                float v2 = fmaxf(d[nt][2] + sb2v[c],   0.f);
                float v3 = fmaxf(d[nt][3] + sb2v[c+1], 0.f);
                __nv_bfloat16 h0,l0,h1,l1;
                split_bf(v0,h0,l0); split_bf(v1,h1,l1);
                *(unsigned*)(sAhi + r*S + c) = packbf(h0,h1);
                *(unsigned*)(sAlo + r*S + c) = packbf(l0,l1);
                split_bf(v2,h0,l0); split_bf(v3,h1,l1);
                *(unsigned*)(sAhi + (r+8)*S + c) = packbf(h0,h1);
                *(unsigned*)(sAlo + (r+8)*S + c) = packbf(l0,l1);
            }
            __syncthreads();
            for (int t = tid; t < 4096; t += 160){
                int o = t & 63, k = t >> 6;
                __nv_bfloat16 h, lo2; split_bf(w3[k*64+o], h, lo2);
                sBhi[o*S+k] = h; sBlo[o*S+k] = lo2;
            }
            __syncthreads();
        }
    }

    __syncthreads();
    #pragma unroll
    for (int nt=0; nt<8; nt++){
        int c = nt*8 + cb;
        sOut[r*68 + c]         = d[nt][0] + sb3v[c];
        sOut[r*68 + c + 1]     = d[nt][1] + sb3v[c+1];
        sOut[(r+8)*68 + c]     = d[nt][2] + sb3v[c];
        sOut[(r+8)*68 + c + 1] = d[nt][3] + sb3v[c+1];
    }
    __syncthreads();
    for (int t = tid; t < 256; t += 160){
        int n = t >> 6, c = t & 63;
        float mx = -FLT_MAX;
        #pragma unroll 5
        for (int e = 0; e < 20; e++)
            mx = fmaxf(mx, sOut[(n*20+e)*68 + c]);
        int gi = blockIdx.x*4 + n;
        g_x1[gi*64 + c] = mx;
        __nv_bfloat16 h, lo2; split_bf(mx, h, lo2);
        g_fhi[gi*256 + c] = h;
        g_flo[gi*256 + c] = lo2;
    }
}

// ---------------- node-level GEMM: 32-node tiles (better SM fill) -----------
__device__ __forceinline__ void uy_gemm_body(
    const float* __restrict__ X, const float* __restrict__ W,
    float* __restrict__ U, float* __restrict__ Y, int OUT)
{
    __shared__ float fbuf[32*33];
    __shared__ float wbuf[32*132];
    int nbase = blockIdx.x * 32;
    int otile = blockIdx.y * 128;
    int tn = threadIdx.x & 15;
    int to = threadIdx.x >> 4;

    float acc[2][8];
    #pragma unroll
    for (int r=0;r<2;r++)
        #pragma unroll
        for (int q=0;q<8;q++) acc[r][q]=0.f;

    for (int kc=0;kc<2;kc++){
        for (int t=threadIdx.x; t<32*32; t+=256){
            int n=t>>5, kk=t&31;
            fbuf[n*33+kk] = X[(nbase+n)*64 + kc*32 + kk];
        }
        for (int t=threadIdx.x; t<32*128; t+=256){
            int kk=t>>7, oloc=t&127;
            int op = otile + oloc;
            int k  = kc*32+kk;
            wbuf[kk*132+oloc] = (op < OUT)
                ? (W[k*OUT + op] - W[(64+k)*OUT + op])
                : W[(64+k)*OUT + (op-OUT)];
        }
        __syncthreads();
        #pragma unroll 4
        for (int kk=0;kk<32;kk++){
            float f0 = fbuf[to*33+kk];
            float f1 = fbuf[(to+16)*33+kk];
            float wv[8];
            #pragma unroll
            for (int q=0;q<8;q++) wv[q] = wbuf[kk*132 + tn + 16*q];
            #pragma unroll
            for (int q=0;q<8;q++){
                acc[0][q] += f0*wv[q];
                acc[1][q] += f1*wv[q];
            }
        }
        __syncthreads();
    }
    #pragma unroll
    for (int r=0;r<2;r++){
        int node = nbase + to + 16*r;
        #pragma unroll
        for (int q=0;q<8;q++){
            int op = otile + tn + 16*q;
            if (op < OUT) U[node*OUT + op]        = acc[r][q];
            else          Y[node*OUT + (op-OUT)]  = acc[r][q];
        }
    }
}

__global__ __launch_bounds__(256) void uy_gemm2_kernel(const float* __restrict__ W){
    uy_gemm_body(g_x1, W, g_u2, g_y2, 64);
}
__global__ __launch_bounds__(256) void uy_gemm3_kernel(const float* __restrict__ W){
    uy_gemm_body(g_x2, W, g_u3, g_y3, 128);
}

// ---------------- gather + elementwise max (+ fused bf16 emission) ----------
__global__ __launch_bounds__(256) void gathermax2_kernel(const float* __restrict__ b2){
    int wd = threadIdx.x >> 5, lane = threadIdx.x & 31;
    int i = blockIdx.x*8 + wd;
    const int* ip = g_idx + i*KNN;
    float2 mx = make_float2(-FLT_MAX, -FLT_MAX);
    #pragma unroll 5
    for (int t=0;t<KNN;t++){
        int j = ip[t];
        float2 v = *(const float2*)(g_y2 + j*64 + lane*2);
        mx.x = fmaxf(mx.x, v.x);
        mx.y = fmaxf(mx.y, v.y);
    }
    float2 u  = *(const float2*)(g_u2 + i*64 + lane*2);
    float2 bb = *(const float2*)(b2 + lane*2);
    float2 o;
    o.x = bb.x + u.x + mx.x;
    o.y = bb.y + u.y + mx.y;
    *(float2*)(g_x2 + i*64 + lane*2) = o;
    __nv_bfloat16 h0,l0,h1,l1;
    split_bf(o.x, h0, l0); split_bf(o.y, h1, l1);
    *(unsigned*)(g_fhi + i*256 + 64 + lane*2) = packbf(h0, h1);
    *(unsigned*)(g_flo + i*256 + 64 + lane*2) = packbf(l0, l1);
}

__global__ __launch_bounds__(256) void gathermax3_kernel(const float* __restrict__ b3){
    int wd = threadIdx.x >> 5, lane = threadIdx.x & 31;
    int i = blockIdx.x*8 + wd;
    const int* ip = g_idx + i*KNN;
    float4 mx = make_float4(-FLT_MAX,-FLT_MAX,-FLT_MAX,-FLT_MAX);
    #pragma unroll 5
    for (int t=0;t<KNN;t++){
        int j = ip[t];
        float4 v = *(const float4*)(g_y3 + j*128 + lane*4);
        mx.x = fmaxf(mx.x, v.x);
        mx.y = fmaxf(mx.y, v.y);
        mx.z = fmaxf(mx.z, v.z);
        mx.w = fmaxf(mx.w, v.w);
    }
    float4 u  = *(const float4*)(g_u3 + i*128 + lane*4);
    float4 bb = *(const float4*)(b3 + lane*4);
    float4 o;
    o.x = bb.x + u.x + mx.x;
    o.y = bb.y + u.y + mx.y;
    o.z = bb.z + u.z + mx.z;
    o.w = bb.w + u.w + mx.w;
    *(float4*)(g_x3 + i*128 + lane*4) = o;
    __nv_bfloat16 h0,l0,h1,l1,h2,l2,h3,l3;
    split_bf(o.x, h0, l0); split_bf(o.y, h1, l1);
    split_bf(o.z, h2, l2); split_bf(o.w, h3, l3);
    unsigned* ph = (unsigned*)(g_fhi + i*256 + 128 + lane*4);
    unsigned* pl = (unsigned*)(g_flo + i*256 + 128 + lane*4);
    ph[0] = packbf(h0, h1); ph[1] = packbf(h2, h3);
    pl[0] = packbf(l0, l1); pl[1] = packbf(l2, l3);
}

// ---------------- lin1 (256->1024) + pool via mma.sync bf16 split-2 ---------
__global__ __launch_bounds__(256) void lin1mma_kernel(const float* __restrict__ l1b)
{
    __shared__ __align__(16) __nv_bfloat16 sAhi[128*40];
    __shared__ __align__(16) __nv_bfloat16 sAlo[128*40];
    __shared__ __align__(16) __nv_bfloat16 sBhi[128*40];
    __shared__ __align__(16) __nv_bfloat16 sBlo[128*40];

    int tid  = threadIdx.x;
    int wid  = tid >> 5, lane = tid & 31;
    int wn   = wid & 1, wo = wid >> 1;
    int nbase = blockIdx.x * 128;
    int obase = blockIdx.y * 128;
    int g     = blockIdx.x >> 4;

    float d[4][4][4];
    #pragma unroll
    for (int mt=0;mt<4;mt++)
        #pragma unroll
        for (int nt=0;nt<4;nt++)
            #pragma unroll
            for (int r=0;r<4;r++) d[mt][nt][r] = 0.f;

    int srow = tid >> 1, shalf = tid & 1;

    for (int kc = 0; kc < 8; kc++){
        {
            size_t fo = (size_t)(nbase + srow)*256 + kc*32 + shalf*16;
            const uint4* pah = (const uint4*)(g_fhi + fo);
            const uint4* pal = (const uint4*)(g_flo + fo);
            uint4 a0 = pah[0], a1 = pah[1];
            uint4 l0 = pal[0], l1 = pal[1];
            size_t wo2 = (size_t)(obase + srow)*256 + kc*32 + shalf*16;
            const uint4* pbh = (const uint4*)(g_whi + wo2);
            const uint4* pbl = (const uint4*)(g_wlo + wo2);
            uint4 b0 = pbh[0], b1 = pbh[1];
            uint4 m0 = pbl[0], m1 = pbl[1];
            int so = srow*40 + shalf*16;
            *(uint4*)(sAhi + so) = a0; *(uint4*)(sAhi + so + 8) = a1;
            *(uint4*)(sAlo + so) = l0; *(uint4*)(sAlo + so + 8) = l1;
            *(uint4*)(sBhi + so) = b0; *(uint4*)(sBhi + so + 8) = b1;
            *(uint4*)(sBlo + so) = m0; *(uint4*)(sBlo + so + 8) = m1;
        }
        __syncthreads();
        #pragma unroll
        for (int ks = 0; ks < 2; ks++){
            int kof = ks*16 + (lane & 3)*2;
            unsigned bh[4][2], bl[4][2];
            #pragma unroll
            for (int nt=0; nt<4; nt++){
                int n = wo*32 + nt*8 + (lane >> 2);
                bh[nt][0] = *(const unsigned*)(sBhi + n*40 + kof);
                bh[nt][1] = *(const unsigned*)(sBhi + n*40 + kof + 8);
                bl[nt][0] = *(const unsigned*)(sBlo + n*40 + kof);
                bl[nt][1] = *(const unsigned*)(sBlo + n*40 + kof + 8);
            }
            unsigned a[4][4];
            #pragma unroll
            for (int mt=0; mt<4; mt++){
                int r = wn*64 + mt*16 + (lane >> 2);
                a[mt][0] = *(const unsigned*)(sAhi + r*40     + kof);
                a[mt][1] = *(const unsigned*)(sAhi + (r+8)*40 + kof);
                a[mt][2] = *(const unsigned*)(sAhi + r*40     + kof + 8);
                a[mt][3] = *(const unsigned*)(sAhi + (r+8)*40 + kof + 8);
            }
            #pragma unroll
            for (int mt=0; mt<4; mt++)
                #pragma unroll
                for (int nt=0; nt<4; nt++)
                    mma_bf16(d[mt][nt], a[mt], bh[nt]);
            #pragma unroll
            for (int mt=0; mt<4; mt++)
                #pragma unroll
                for (int nt=0; nt<4; nt++)
                    mma_bf16(d[mt][nt], a[mt], bl[nt]);
            #pragma unroll
            for (int mt=0; mt<4; mt++){
                int r = wn*64 + mt*16 + (lane >> 2);
                a[mt][0] = *(const unsigned*)(sAlo + r*40     + kof);
                a[mt][1] = *(const unsigned*)(sAlo + (r+8)*40 + kof);
                a[mt][2] = *(const unsigned*)(sAlo + r*40     + kof + 8);
                a[mt][3] = *(const unsigned*)(sAlo + (r+8)*40 + kof + 8);
            }
            #pragma unroll
            for (int mt=0; mt<4; mt++)
                #pragma unroll
                for (int nt=0; nt<4; nt++)
                    mma_bf16(d[mt][nt], a[mt], bh[nt]);
        }
        __syncthreads();
    }

    #pragma unroll
    for (int nt=0; nt<4; nt++){
        float m0 = -FLT_MAX, m1 = -FLT_MAX;
        #pragma unroll
        for (int mt=0; mt<4; mt++){
            m0 = fmaxf(m0, fmaxf(d[mt][nt][0], d[mt][nt][2]));
            m1 = fmaxf(m1, fmaxf(d[mt][nt][1], d[mt][nt][3]));
        }
        #pragma unroll
        for (int off=4; off<32; off<<=1){
            m0 = fmaxf(m0, __shfl_xor_sync(0xFFFFFFFFu, m0, off));
            m1 = fmaxf(m1, __shfl_xor_sync(0xFFFFFFFFu, m1, off));
        }
        if (lane < 4){
            int col = obase + wo*32 + nt*8 + lane*2;
            atomicMaxFloat(&g_out2[g*1024 + col    ], m0 + l1b[col]);
            atomicMaxFloat(&g_out2[g*1024 + col + 1], m1 + l1b[col+1]);
        }
    }
}

// ---------------- head1: 1024->512 + ReLU ------------------------------------
__global__ __launch_bounds__(256) void head1_kernel(
    const float* __restrict__ m1w, const float* __restrict__ m1b)
{
    __shared__ float v[1024];
    __shared__ float partial[256];
    int g     = blockIdx.x >> 2;
    int chunk = blockIdx.x & 3;
    for (int t=threadIdx.x; t<1024; t+=256) v[t] = g_out2[g*1024+t];
    __syncthreads();
    int o    = chunk*128 + (threadIdx.x & 127);
    int half = threadIdx.x >> 7;
    float a = 0.f;
    #pragma unroll 8
    for (int k=half*512; k<half*512+512; k++) a += v[k]*m1w[k*512+o];
    partial[threadIdx.x] = a;
    __syncthreads();
    if (threadIdx.x < 128){
        float s = partial[threadIdx.x] + partial[threadIdx.x+128] + m1b[o];
        g_h1[g*512+o] = fmaxf(s, 0.f);
    }
}

// ---------------- head2: 512->256->10 + log_softmax -------------------------
__global__ __launch_bounds__(256) void head2_kernel(
    const float* __restrict__ m2w, const float* __restrict__ m2b,
    const float* __restrict__ m3w, const float* __restrict__ m3b,
    float* __restrict__ out)
{
    __shared__ float h1[512];
    __shared__ float h2[256];
    __shared__ float z[10];
    int g = blockIdx.x;
    for (int t=threadIdx.x; t<512; t+=256) h1[t] = g_h1[g*512+t];
    __syncthreads();
    {
        int o = threadIdx.x;
        float a = m2b[o];
        #pragma unroll 8
        for (int k=0;k<512;k++) a += h1[k]*m2w[k*256+o];
        h2[o] = fmaxf(a, 0.f);
    }
    __syncthreads();
    if (threadIdx.x < 10){
        float a = m3b[threadIdx.x];
        for (int k=0;k<256;k++) a += h2[k]*m3w[k*10+threadIdx.x];
        z[threadIdx.x] = a;
    }
    __syncthreads();
    if (threadIdx.x == 0){
        float m = -FLT_MAX;
        for (int c=0;c<10;c++) m = fmaxf(m, z[c]);
        float s = 0.f;
        for (int c=0;c<10;c++) s += expf(z[c]-m);
        float l = logf(s);
        for (int c=0;c<10;c++) out[g*10+c] = z[c]-m-l;
    }
}

// ---------------- launch ----------------------------------------------------
extern "C" void kernel_launch(void* const* d_in, const int* in_sizes, int n_in,
                              void* d_out, int out_size)
{
    const float* pos  = (const float*)d_in[0];
    const float* xf   = (const float*)d_in[1];
    const float* c1w1 = (const float*)d_in[3];
    const float* c1b1 = (const float*)d_in[4];
    const float* c1w2 = (const float*)d_in[5];
    const float* c1b2 = (const float*)d_in[6];
    const float* c1w3 = (const float*)d_in[7];
    const float* c1b3 = (const float*)d_in[8];
    const float* c2w  = (const float*)d_in[9];
    const float* c2b  = (const float*)d_in[10];
    const float* c3w  = (const float*)d_in[11];
    const float* c3b  = (const float*)d_in[12];
    const float* l1w  = (const float*)d_in[13];
    const float* l1b  = (const float*)d_in[14];
    const float* m1w  = (const float*)d_in[15];
    const float* m1b  = (const float*)d_in[16];
    const float* m2w  = (const float*)d_in[17];
    const float* m2b  = (const float*)d_in[18];
    const float* m3w  = (const float*)d_in[19];
    const float* m3b  = (const float*)d_in[20];
    float* out = (float*)d_out;

    prep_kernel<<<NTOT/256, 256>>>(pos, xf);                       // 0
    knn_kernel<<<NTOT/16, 512>>>();                                // 1
    conv1_kernel<<<NTOT/4, 160>>>(c1w1,c1b1,c1w2,c1b2,c1w3,c1b3);  // 2
    uy_gemm2_kernel<<<dim3(NTOT/32, 1), 256>>>(c2w);               // 3 (profiled)
    gathermax2_kernel<<<NTOT/8, 256>>>(c2b);                       // 4
    uy_gemm3_kernel<<<dim3(NTOT/32, 2), 256>>>(c3w);               // 5
    gathermax3_kernel<<<NTOT/8, 256>>>(c3b);                       // 6
    wconv_kernel<<<1024*256/256, 256>>>(l1w);                      // 7
    lin1mma_kernel<<<dim3(NTOT/128, 8), 256>>>(l1b);               // 8
    head1_kernel<<<B_*4, 256>>>(m1w, m1b);                         // 9
    head2_kernel<<<B_, 256>>>(m2w, m2b, m3w, m3b, out);            // 10
}

// round 17
// speedup vs baseline: 1.0190x; 1.0190x over previous
#include <cuda_runtime.h>
#include <cuda_bf16.h>
#include <cfloat>
#include <math.h>

#define B_   16
#define NPER 2048
#define NTOT (B_*NPER)
#define KNN  20

typedef unsigned long long ull;

// ---------------- scratch (device globals; no runtime allocation) ----------
__device__ float4 g_x0[NTOT];
__device__ float  g_sn[NTOT];
__device__ int    g_idx[NTOT*KNN];
__device__ float  g_x1[NTOT*64];
__device__ float  g_x2[NTOT*64];
__device__ float  g_x3[NTOT*128];
__device__ float  g_u2[NTOT*64];
__device__ float  g_y2[NTOT*64];
__device__ float  g_u3[NTOT*128];
__device__ float  g_y3[NTOT*128];
__device__ float  g_out2[B_*1024];
__device__ float  g_h1[B_*512];
__device__ __align__(16) __nv_bfloat16 g_fhi[NTOT*256];
__device__ __align__(16) __nv_bfloat16 g_flo[NTOT*256];
__device__ __align__(16) __nv_bfloat16 g_whi[1024*256];
__device__ __align__(16) __nv_bfloat16 g_wlo[1024*256];

__device__ __forceinline__ void atomicMaxFloat(float* addr, float v){
    if (v >= 0.f) atomicMax((int*)addr, __float_as_int(v));
    else          atomicMin((unsigned int*)addr, (unsigned int)__float_as_int(v));
}
__device__ __forceinline__ unsigned packbf(__nv_bfloat16 a, __nv_bfloat16 b){
    __nv_bfloat162 t = __halves2bfloat162(a, b);
    return *reinterpret_cast<unsigned*>(&t);
}
__device__ __forceinline__ void split_bf(float x, __nv_bfloat16& h, __nv_bfloat16& l){
    h = __float2bfloat16(x);
    l = __float2bfloat16(x - __bfloat162float(h));
}
// order-preserving float<->uint encoding (total order, matches float <)
__device__ __forceinline__ unsigned encf(float f){
    unsigned b = __float_as_uint(f);
    return (b & 0x80000000u) ? ~b : (b | 0x80000000u);
}
__device__ __forceinline__ float decf(unsigned u){
    unsigned b = (u & 0x80000000u) ? (u & 0x7FFFFFFFu) : ~u;
    return __uint_as_float(b);
}
// mma.sync m16n8k16 bf16 (HMMA path, base sm_80+ feature)
__device__ __forceinline__ void mma_bf16(float* d, const unsigned* a, const unsigned* b){
    asm volatile("mma.sync.aligned.m16n8k16.row.col.f32.bf16.bf16.f32 "
        "{%0,%1,%2,%3}, {%4,%5,%6,%7}, {%8,%9}, {%0,%1,%2,%3};"
        : "+f"(d[0]), "+f"(d[1]), "+f"(d[2]), "+f"(d[3])
        : "r"(a[0]), "r"(a[1]), "r"(a[2]), "r"(a[3]), "r"(b[0]), "r"(b[1]));
}

// ---------------- prep: x0 + sn + out2 init (fused) -------------------------
__global__ __launch_bounds__(256) void prep_kernel(const float* __restrict__ pos,
                                                   const float* __restrict__ xf){
    int i = blockIdx.x*256 + threadIdx.x;
    float4 p = make_float4(pos[i*3+0], pos[i*3+1], pos[i*3+2], xf[i]);
    g_x0[i] = p;
    g_sn[i] = p.x*p.x + p.y*p.y + p.z*p.z + p.w*p.w;
    if (i < B_*1024) g_out2[i] = -FLT_MAX;
}

// ---------------- weight conversion: l1w -> bf16 hi/lo, [o][k] transposed ---
__global__ __launch_bounds__(256) void wconv_kernel(const float* __restrict__ l1w){
    int i = blockIdx.x*256 + threadIdx.x;    // 1024*256
    int o = i & 1023, k = i >> 10;
    float w = l1w[k*1024 + o];
    __nv_bfloat16 h, l; split_bf(w, h, l);
    g_whi[o*256 + k] = h;
    g_wlo[o*256 + k] = l;
}

// ---------------- kNN: warp per query, paired candidates + redux worst ------
__global__ __launch_bounds__(512) void knn_kernel()
{
    __shared__ float4 sp[NPER];
    __shared__ float  sn[NPER];
    const unsigned FULL = 0xFFFFFFFFu;
    int b    = blockIdx.x >> 7;
    int base = b * NPER;
    for (int j = threadIdx.x; j < NPER; j += 512){
        sp[j] = g_x0[base+j];
        sn[j] = g_sn[base+j];
    }
    __syncthreads();

    int lane = threadIdx.x & 31;
    int q    = (blockIdx.x & 127)*16 + (threadIdx.x >> 5);
    float4 p = sp[q];
    float  pn = sn[q];

    float bd = FLT_MAX;
    int   bi = 0;
    float worst = FLT_MAX;

    for (int s = 0; s < NPER; s += 64){
        int j0 = s + lane, j1 = s + 32 + lane;
        float4 c0 = sp[j0];
        float4 c1 = sp[j1];
        float d0 = pn + sn[j0] - 2.f*(p.x*c0.x + p.y*c0.y + p.z*c0.z + p.w*c0.w);
        float d1 = pn + sn[j1] - 2.f*(p.x*c1.x + p.y*c1.y + p.z*c1.z + p.w*c1.w);
        if (j0 == q) d0 = FLT_MAX;
        if (j1 == q) d1 = FLT_MAX;
        unsigned m = __ballot_sync(FULL, fminf(d0, d1) < worst);
        while (m){
            int src = __ffs(m) - 1; m &= m - 1;
            float e0 = __shfl_sync(FULL, d0, src);
            float e1 = __shfl_sync(FULL, d1, src);
            if (e0 < worst){
                unsigned wm = __ballot_sync(FULL, (lane < KNN) && (bd == worst));
                int slot = __ffs(wm) - 1;
                if (lane == slot){ bd = e0; bi = s + src; }
                worst = decf(__reduce_max_sync(FULL, (lane < KNN) ? encf(bd) : 0u));
            }
            if (e1 < worst){
                unsigned wm = __ballot_sync(FULL, (lane < KNN) && (bd == worst));
                int slot = __ffs(wm) - 1;
                if (lane == slot){ bd = e1; bi = s + 32 + src; }
                worst = decf(__reduce_max_sync(FULL, (lane < KNN) ? encf(bd) : 0u));
            }
        }
    }
    if (lane < KNN) g_idx[(base+q)*KNN + lane] = base + bi;
}

// ---------------- EdgeConv1 via HMMA (R15 proven) ---------------------------
__global__ __launch_bounds__(160) void conv1_kernel(
    const float* __restrict__ w1, const float* __restrict__ b1,
    const float* __restrict__ w2, const float* __restrict__ b2,
    const float* __restrict__ w3, const float* __restrict__ b3)
{
    const int S = 72;
    __shared__ __align__(16) __nv_bfloat16 sA[2*80*72];
    __shared__ __align__(16) __nv_bfloat16 sB[2*64*72];
    __shared__ float sW1b[4*64], sW1d[4*64], sb1v[64], sb2v[64], sb3v[64];
    __nv_bfloat16* sAhi = sA;
    __nv_bfloat16* sAlo = sA + 80*S;
    __nv_bfloat16* sBhi = sB;
    __nv_bfloat16* sBlo = sB + 64*S;
    float* sOut = (float*)sA;

    int tid = threadIdx.x, w = tid >> 5, l = tid & 31;

    for (int t = tid; t < 256; t += 160){
        int c = t >> 6, o = t & 63;
        float top = w1[c*64+o], bot = w1[(c+4)*64+o];
        sW1b[t] = bot; sW1d[t] = top - bot;
    }
    if (tid < 64){ sb1v[tid]=b1[tid]; sb2v[tid]=b2[tid]; sb3v[tid]=b3[tid]; }
    for (int t = tid; t < 4096; t += 160){
        int o = t & 63, k = t >> 6;
        __nv_bfloat16 h, lo2; split_bf(w2[k*64+o], h, lo2);
        sBhi[o*S+k] = h; sBlo[o*S+k] = lo2;
    }
    __syncthreads();

    {
        int row   = w*16 + (l>>1);
        int chalf = (l&1)*32;
        int node  = row / 20;
        int e     = row - node*20;
        int gi    = blockIdx.x*4 + node;
        int j     = g_idx[gi*KNN + e];
        float4 xi = g_x0[gi];
        float4 xj = g_x0[j];
        for (int c = chalf; c < chalf+32; c++){
            float v = sb1v[c]
                + xi.x*sW1d[c] + xi.y*sW1d[64+c] + xi.z*sW1d[128+c] + xi.w*sW1d[192+c]
                + xj.x*sW1b[c] + xj.y*sW1b[64+c] + xj.z*sW1b[128+c] + xj.w*sW1b[192+c];
            v = fmaxf(v, 0.f);
            __nv_bfloat16 h, lo2; split_bf(v, h, lo2);
            sAhi[row*S + c] = h;
            sAlo[row*S + c] = lo2;
        }
    }
    __syncthreads();

    float d[8][4];
    int r  = w*16 + (l>>2);
    int cb = (l&3)*2;

    for (int layer = 0; layer < 2; layer++){
        #pragma unroll
        for (int nt=0; nt<8; nt++)
            #pragma unroll
            for (int q=0;q<4;q++) d[nt][q] = 0.f;

        #pragma unroll
        for (int ks = 0; ks < 4; ks++){
            int kof = ks*16 + cb;
            unsigned ah[4], bh[8][2], bl2[8][2];
            ah[0] = *(const unsigned*)(sAhi + r*S     + kof);
            ah[1] = *(const unsigned*)(sAhi + (r+8)*S + kof);
            ah[2] = *(const unsigned*)(sAhi + r*S     + kof + 8);
            ah[3] = *(const unsigned*)(sAhi + (r+8)*S + kof + 8);
            #pragma unroll
            for (int nt=0; nt<8; nt++){
                int n = nt*8 + (l>>2);
                bh[nt][0]  = *(const unsigned*)(sBhi + n*S + kof);
                bh[nt][1]  = *(const unsigned*)(sBhi + n*S + kof + 8);
                bl2[nt][0] = *(const unsigned*)(sBlo + n*S + kof);
                bl2[nt][1] = *(const unsigned*)(sBlo + n*S + kof + 8);
            }
            #pragma unroll
            for (int nt=0; nt<8; nt++) mma_bf16(d[nt], ah, bh[nt]);
            #pragma unroll
            for (int nt=0; nt<8; nt++) mma_bf16(d[nt], ah, bl2[nt]);
            unsigned al[4];
            al[0] = *(const unsigned*)(sAlo + r*S     + kof);
            al[1] = *(const unsigned*)(sAlo + (r+8)*S + kof);
            al[2] = *(const unsigned*)(sAlo + r*S     + kof + 8);
            al[3] = *(const unsigned*)(sAlo + (r+8)*S + kof + 8);
            #pragma unroll
            for (int nt=0; nt<8; nt++) mma_bf16(d[nt], al, bh[nt]);
        }

        if (layer == 0){
            #pragma unroll
            for (int nt=0; nt<8; nt++){
                int c = nt*8 + cb;
                float v0 = fmaxf(d[nt][0] + sb2v[c],   0.f);
                float v1 = fmaxf(d[nt][1] + sb2v[c+1], 0.f);
                float v2 = fmaxf(d[nt][2] + sb2v[c],   0.f);
                float v3 = fmaxf(d[nt][3] + sb2v[c+1], 0.f);
                __nv_bfloat16 h0,l0,h1,l1;
                split_bf(v0,h0,l0); split_bf(v1,h1,l1);
                *(unsigned*)(sAhi + r*S + c) = packbf(h0,h1);
                *(unsigned*)(sAlo + r*S + c) = packbf(l0,l1);
                split_bf(v2,h0,l0); split_bf(v3,h1,l1);
                *(unsigned*)(sAhi + (r+8)*S + c) = packbf(h0,h1);
                *(unsigned*)(sAlo + (r+8)*S + c) = packbf(l0,l1);
            }
            __syncthreads();
            for (int t = tid; t < 4096; t += 160){
                int o = t & 63, k = t >> 6;
                __nv_bfloat16 h, lo2; split_bf(w3[k*64+o], h, lo2);
                sBhi[o*S+k] = h; sBlo[o*S+k] = lo2;
            }
            __syncthreads();
        }
    }

    __syncthreads();
    #pragma unroll
    for (int nt=0; nt<8; nt++){
        int c = nt*8 + cb;
        sOut[r*68 + c]         = d[nt][0] + sb3v[c];
        sOut[r*68 + c + 1]     = d[nt][1] + sb3v[c+1];
        sOut[(r+8)*68 + c]     = d[nt][2] + sb3v[c];
        sOut[(r+8)*68 + c + 1] = d[nt][3] + sb3v[c+1];
    }
    __syncthreads();
    for (int t = tid; t < 256; t += 160){
        int n = t >> 6, c = t & 63;
        float mx = -FLT_MAX;
        #pragma unroll 5
        for (int e = 0; e < 20; e++)
            mx = fmaxf(mx, sOut[(n*20+e)*68 + c]);
        int gi = blockIdx.x*4 + n;
        g_x1[gi*64 + c] = mx;
        __nv_bfloat16 h, lo2; split_bf(mx, h, lo2);
        g_fhi[gi*256 + c] = h;
        g_flo[gi*256 + c] = lo2;
    }
}

// ---------------- node-level GEMM: 64-node tiles (R14 proven) ---------------
__device__ __forceinline__ void uy_gemm_body(
    const float* __restrict__ X, const float* __restrict__ W,
    float* __restrict__ U, float* __restrict__ Y, int OUT)
{
    __shared__ float fbuf[64*33];
    __shared__ float wbuf[32*132];
    int nbase = blockIdx.x * 64;
    int otile = blockIdx.y * 128;
    int tn = threadIdx.x & 15;
    int to = threadIdx.x >> 4;

    float acc[4][8];
    #pragma unroll
    for (int r=0;r<4;r++)
        #pragma unroll
        for (int q=0;q<8;q++) acc[r][q]=0.f;

    for (int kc=0;kc<2;kc++){
        for (int t=threadIdx.x; t<64*32; t+=256){
            int n=t>>5, kk=t&31;
            fbuf[n*33+kk] = X[(nbase+n)*64 + kc*32 + kk];
        }
        for (int t=threadIdx.x; t<32*128; t+=256){
            int kk=t>>7, oloc=t&127;
            int op = otile + oloc;
            int k  = kc*32+kk;
            wbuf[kk*132+oloc] = (op < OUT)
                ? (W[k*OUT + op] - W[(64+k)*OUT + op])
                : W[(64+k)*OUT + (op-OUT)];
        }
        __syncthreads();
        #pragma unroll 4
        for (int kk=0;kk<32;kk++){
            float f[4];
            #pragma unroll
            for (int r=0;r<4;r++) f[r] = fbuf[(to+16*r)*33+kk];
            float wv[8];
            #pragma unroll
            for (int q=0;q<8;q++) wv[q] = wbuf[kk*132 + tn + 16*q];
            #pragma unroll
            for (int r=0;r<4;r++)
                #pragma unroll
                for (int q=0;q<8;q++) acc[r][q] += f[r]*wv[q];
        }
        __syncthreads();
    }
    #pragma unroll
    for (int r=0;r<4;r++){
        int node = nbase + to + 16*r;
        #pragma unroll
        for (int q=0;q<8;q++){
            int op = otile + tn + 16*q;
            if (op < OUT) U[node*OUT + op]        = acc[r][q];
            else          Y[node*OUT + (op-OUT)]  = acc[r][q];
        }
    }
}

__global__ __launch_bounds__(256) void uy_gemm2_kernel(const float* __restrict__ W){
    uy_gemm_body(g_x1, W, g_u2, g_y2, 64);
}
__global__ __launch_bounds__(256) void uy_gemm3_kernel(const float* __restrict__ W){
    uy_gemm_body(g_x2, W, g_u3, g_y3, 128);
}

// ---------------- gather + elementwise max (+ fused bf16 emission) ----------
__global__ __launch_bounds__(256) void gathermax2_kernel(const float* __restrict__ b2){
    int wd = threadIdx.x >> 5, lane = threadIdx.x & 31;
    int i = blockIdx.x*8 + wd;
    const int* ip = g_idx + i*KNN;
    float2 mx = make_float2(-FLT_MAX, -FLT_MAX);
    #pragma unroll 5
    for (int t=0;t<KNN;t++){
        int j = ip[t];
        float2 v = *(const float2*)(g_y2 + j*64 + lane*2);
        mx.x = fmaxf(mx.x, v.x);
        mx.y = fmaxf(mx.y, v.y);
    }
    float2 u  = *(const float2*)(g_u2 + i*64 + lane*2);
    float2 bb = *(const float2*)(b2 + lane*2);
    float2 o;
    o.x = bb.x + u.x + mx.x;
    o.y = bb.y + u.y + mx.y;
    *(float2*)(g_x2 + i*64 + lane*2) = o;
    __nv_bfloat16 h0,l0,h1,l1;
    split_bf(o.x, h0, l0); split_bf(o.y, h1, l1);
    *(unsigned*)(g_fhi + i*256 + 64 + lane*2) = packbf(h0, h1);
    *(unsigned*)(g_flo + i*256 + 64 + lane*2) = packbf(l0, l1);
}

__global__ __launch_bounds__(256) void gathermax3_kernel(const float* __restrict__ b3){
    int wd = threadIdx.x >> 5, lane = threadIdx.x & 31;
    int i = blockIdx.x*8 + wd;
    const int* ip = g_idx + i*KNN;
    float4 mx = make_float4(-FLT_MAX,-FLT_MAX,-FLT_MAX,-FLT_MAX);
    #pragma unroll 5
    for (int t=0;t<KNN;t++){
        int j = ip[t];
        float4 v = *(const float4*)(g_y3 + j*128 + lane*4);
        mx.x = fmaxf(mx.x, v.x);
        mx.y = fmaxf(mx.y, v.y);
        mx.z = fmaxf(mx.z, v.z);
        mx.w = fmaxf(mx.w, v.w);
    }
    float4 u  = *(const float4*)(g_u3 + i*128 + lane*4);
    float4 bb = *(const float4*)(b3 + lane*4);
    float4 o;
    o.x = bb.x + u.x + mx.x;
    o.y = bb.y + u.y + mx.y;
    o.z = bb.z + u.z + mx.z;
    o.w = bb.w + u.w + mx.w;
    *(float4*)(g_x3 + i*128 + lane*4) = o;
    __nv_bfloat16 h0,l0,h1,l1,h2,l2,h3,l3;
    split_bf(o.x, h0, l0); split_bf(o.y, h1, l1);
    split_bf(o.z, h2, l2); split_bf(o.w, h3, l3);
    unsigned* ph = (unsigned*)(g_fhi + i*256 + 128 + lane*4);
    unsigned* pl = (unsigned*)(g_flo + i*256 + 128 + lane*4);
    ph[0] = packbf(h0, h1); ph[1] = packbf(h2, h3);
    pl[0] = packbf(l0, l1); pl[1] = packbf(l2, l3);
}

// ---------------- lin1 (256->1024) + pool via mma.sync bf16 split-2 ---------
__global__ __launch_bounds__(256) void lin1mma_kernel(const float* __restrict__ l1b)
{
    __shared__ __align__(16) __nv_bfloat16 sAhi[128*40];
    __shared__ __align__(16) __nv_bfloat16 sAlo[128*40];
    __shared__ __align__(16) __nv_bfloat16 sBhi[128*40];
    __shared__ __align__(16) __nv_bfloat16 sBlo[128*40];

    int tid  = threadIdx.x;
    int wid  = tid >> 5, lane = tid & 31;
    int wn   = wid & 1, wo = wid >> 1;
    int nbase = blockIdx.x * 128;
    int obase = blockIdx.y * 128;
    int g     = blockIdx.x >> 4;

    float d[4][4][4];
    #pragma unroll
    for (int mt=0;mt<4;mt++)
        #pragma unroll
        for (int nt=0;nt<4;nt++)
            #pragma unroll
            for (int r=0;r<4;r++) d[mt][nt][r] = 0.f;

    int srow = tid >> 1, shalf = tid & 1;

    for (int kc = 0; kc < 8; kc++){
        {
            size_t fo = (size_t)(nbase + srow)*256 + kc*32 + shalf*16;
            const uint4* pah = (const uint4*)(g_fhi + fo);
            const uint4* pal = (const uint4*)(g_flo + fo);
            uint4 a0 = pah[0], a1 = pah[1];
            uint4 l0 = pal[0], l1 = pal[1];
            size_t wo2 = (size_t)(obase + srow)*256 + kc*32 + shalf*16;
            const uint4* pbh = (const uint4*)(g_whi + wo2);
            const uint4* pbl = (const uint4*)(g_wlo + wo2);
            uint4 b0 = pbh[0], b1 = pbh[1];
            uint4 m0 = pbl[0], m1 = pbl[1];
            int so = srow*40 + shalf*16;
            *(uint4*)(sAhi + so) = a0; *(uint4*)(sAhi + so + 8) = a1;
            *(uint4*)(sAlo + so) = l0; *(uint4*)(sAlo + so + 8) = l1;
            *(uint4*)(sBhi + so) = b0; *(uint4*)(sBhi + so + 8) = b1;
            *(uint4*)(sBlo + so) = m0; *(uint4*)(sBlo + so + 8) = m1;
        }
        __syncthreads();
        #pragma unroll
        for (int ks = 0; ks < 2; ks++){
            int kof = ks*16 + (lane & 3)*2;
            unsigned bh[4][2], bl[4][2];
            #pragma unroll
            for (int nt=0; nt<4; nt++){
                int n = wo*32 + nt*8 + (lane >> 2);
                bh[nt][0] = *(const unsigned*)(sBhi + n*40 + kof);
                bh[nt][1] = *(const unsigned*)(sBhi + n*40 + kof + 8);
                bl[nt][0] = *(const unsigned*)(sBlo + n*40 + kof);
                bl[nt][1] = *(const unsigned*)(sBlo + n*40 + kof + 8);
            }
            unsigned a[4][4];
            #pragma unroll
            for (int mt=0; mt<4; mt++){
                int r = wn*64 + mt*16 + (lane >> 2);
                a[mt][0] = *(const unsigned*)(sAhi + r*40     + kof);
                a[mt][1] = *(const unsigned*)(sAhi + (r+8)*40 + kof);
                a[mt][2] = *(const unsigned*)(sAhi + r*40     + kof + 8);
                a[mt][3] = *(const unsigned*)(sAhi + (r+8)*40 + kof + 8);
            }
            #pragma unroll
            for (int mt=0; mt<4; mt++)
                #pragma unroll
                for (int nt=0; nt<4; nt++)
                    mma_bf16(d[mt][nt], a[mt], bh[nt]);
            #pragma unroll
            for (int mt=0; mt<4; mt++)
                #pragma unroll
                for (int nt=0; nt<4; nt++)
                    mma_bf16(d[mt][nt], a[mt], bl[nt]);
            #pragma unroll
            for (int mt=0; mt<4; mt++){
                int r = wn*64 + mt*16 + (lane >> 2);
                a[mt][0] = *(const unsigned*)(sAlo + r*40     + kof);
                a[mt][1] = *(const unsigned*)(sAlo + (r+8)*40 + kof);
                a[mt][2] = *(const unsigned*)(sAlo + r*40     + kof + 8);
                a[mt][3] = *(const unsigned*)(sAlo + (r+8)*40 + kof + 8);
            }
            #pragma unroll
            for (int mt=0; mt<4; mt++)
                #pragma unroll
                for (int nt=0; nt<4; nt++)
                    mma_bf16(d[mt][nt], a[mt], bh[nt]);
        }
        __syncthreads();
    }

    #pragma unroll
    for (int nt=0; nt<4; nt++){
        float m0 = -FLT_MAX, m1 = -FLT_MAX;
        #pragma unroll
        for (int mt=0; mt<4; mt++){
            m0 = fmaxf(m0, fmaxf(d[mt][nt][0], d[mt][nt][2]));
            m1 = fmaxf(m1, fmaxf(d[mt][nt][1], d[mt][nt][3]));
        }
        #pragma unroll
        for (int off=4; off<32; off<<=1){
            m0 = fmaxf(m0, __shfl_xor_sync(0xFFFFFFFFu, m0, off));
            m1 = fmaxf(m1, __shfl_xor_sync(0xFFFFFFFFu, m1, off));
        }
        if (lane < 4){
            int col = obase + wo*32 + nt*8 + lane*2;
            atomicMaxFloat(&g_out2[g*1024 + col    ], m0 + l1b[col]);
            atomicMaxFloat(&g_out2[g*1024 + col + 1], m1 + l1b[col+1]);
        }
    }
}

// ---------------- head1: 1024->512 + ReLU ------------------------------------
__global__ __launch_bounds__(256) void head1_kernel(
    const float* __restrict__ m1w, const float* __restrict__ m1b)
{
    __shared__ float v[1024];
    __shared__ float partial[256];
    int g     = blockIdx.x >> 2;
    int chunk = blockIdx.x & 3;
    for (int t=threadIdx.x; t<1024; t+=256) v[t] = g_out2[g*1024+t];
    __syncthreads();
    int o    = chunk*128 + (threadIdx.x & 127);
    int half = threadIdx.x >> 7;
    float a = 0.f;
    #pragma unroll 8
    for (int k=half*512; k<half*512+512; k++) a += v[k]*m1w[k*512+o];
    partial[threadIdx.x] = a;
    __syncthreads();
    if (threadIdx.x < 128){
        float s = partial[threadIdx.x] + partial[threadIdx.x+128] + m1b[o];
        g_h1[g*512+o] = fmaxf(s, 0.f);
    }
}

// ---------------- head2: 512->256->10 + log_softmax -------------------------
__global__ __launch_bounds__(256) void head2_kernel(
    const float* __restrict__ m2w, const float* __restrict__ m2b,
    const float* __restrict__ m3w, const float* __restrict__ m3b,
    float* __restrict__ out)
{
    __shared__ float h1[512];
    __shared__ float h2[256];
    __shared__ float z[10];
    int g = blockIdx.x;
    for (int t=threadIdx.x; t<512; t+=256) h1[t] = g_h1[g*512+t];
    __syncthreads();
    {
        int o = threadIdx.x;
        float a = m2b[o];
        #pragma unroll 8
        for (int k=0;k<512;k++) a += h1[k]*m2w[k*256+o];
        h2[o] = fmaxf(a, 0.f);
    }
    __syncthreads();
    if (threadIdx.x < 10){
        float a = m3b[threadIdx.x];
        for (int k=0;k<256;k++) a += h2[k]*m3w[k*10+threadIdx.x];
        z[threadIdx.x] = a;
    }
    __syncthreads();
    if (threadIdx.x == 0){
        float m = -FLT_MAX;
        for (int c=0;c<10;c++) m = fmaxf(m, z[c]);
        float s = 0.f;
        for (int c=0;c<10;c++) s += expf(z[c]-m);
        float l = logf(s);
        for (int c=0;c<10;c++) out[g*10+c] = z[c]-m-l;
    }
}

// ---------------- launch ----------------------------------------------------
extern "C" void kernel_launch(void* const* d_in, const int* in_sizes, int n_in,
                              void* d_out, int out_size)
{
    const float* pos  = (const float*)d_in[0];
    const float* xf   = (const float*)d_in[1];
    const float* c1w1 = (const float*)d_in[3];
    const float* c1b1 = (const float*)d_in[4];
    const float* c1w2 = (const float*)d_in[5];
    const float* c1b2 = (const float*)d_in[6];
    const float* c1w3 = (const float*)d_in[7];
    const float* c1b3 = (const float*)d_in[8];
    const float* c2w  = (const float*)d_in[9];
    const float* c2b  = (const float*)d_in[10];
    const float* c3w  = (const float*)d_in[11];
    const float* c3b  = (const float*)d_in[12];
    const float* l1w  = (const float*)d_in[13];
    const float* l1b  = (const float*)d_in[14];
    const float* m1w  = (const float*)d_in[15];
    const float* m1b  = (const float*)d_in[16];
    const float* m2w  = (const float*)d_in[17];
    const float* m2b  = (const float*)d_in[18];
    const float* m3w  = (const float*)d_in[19];
    const float* m3b  = (const float*)d_in[20];
    float* out = (float*)d_out;

    prep_kernel<<<NTOT/256, 256>>>(pos, xf);                       // 0
    knn_kernel<<<NTOT/16, 512>>>();                                // 1
    conv1_kernel<<<NTOT/4, 160>>>(c1w1,c1b1,c1w2,c1b2,c1w3,c1b3);  // 2
    uy_gemm2_kernel<<<dim3(NTOT/64, 1), 256>>>(c2w);               // 3 (profiled)
    gathermax2_kernel<<<NTOT/8, 256>>>(c2b);                       // 4
    uy_gemm3_kernel<<<dim3(NTOT/64, 2), 256>>>(c3w);               // 5
    gathermax3_kernel<<<NTOT/8, 256>>>(c3b);                       // 6
    wconv_kernel<<<1024*256/256, 256>>>(l1w);                      // 7
    lin1mma_kernel<<<dim3(NTOT/128, 8), 256>>>(l1b);               // 8
    head1_kernel<<<B_*4, 256>>>(m1w, m1b);                         // 9
    head2_kernel<<<B_, 256>>>(m2w, m2b, m3w, m3b, out);            // 10
}